// round 4
// baseline (speedup 1.0000x reference)
#include <cuda_runtime.h>
#include <math.h>

// Problem constants (fixed by the dataset)
#define B_ 4
#define S_ 256
#define E_ 256
#define H_ 128
#define N_ (B_ * S_)   // 1024 rows total

// Scratch (static device arrays; allocation-free per harness rules)
__device__ float g_ampq[N_ * E_];
__device__ float g_ampk[N_ * E_];
__device__ float g_V[N_ * H_];
__device__ float g_Pq[N_ * E_];
__device__ float g_Pk[N_ * E_];
__device__ float g_entq[N_];   // sum_e P * lg2(P + 1e-10)
__device__ float g_entk[N_];

// ---------------------------------------------------------------------------
// Kernel 1: C[1024, 640] = x[1024,256] @ [Wq;Wk;Wv]^T   (region per f-tile)
// 64x64 CTA tile, 256 threads, 4x4 micro-tile, k-chunk 32, smem transposed
// so compute reads are float4 (2 LDS.128 + 16 FFMA per kk).
// ---------------------------------------------------------------------------
__global__ __launch_bounds__(256) void k1_gemm(
    const float* __restrict__ x,
    const float* __restrict__ Wq,
    const float* __restrict__ Wk,
    const float* __restrict__ Wv)
{
    __shared__ float As[32][68];  // [k][m], pad 4 keeps float4 alignment
    __shared__ float Bs[32][68];  // [k][f]

    const int m0 = blockIdx.x * 64;       // row tile (0..15)
    const int f0 = blockIdx.y * 64;       // f tile (0..9) over concat 640

    const float* Wp; float* outp; int fo, ostride;
    if (f0 < 256)      { Wp = Wq; fo = f0;       outp = g_ampq; ostride = E_; }
    else if (f0 < 512) { Wp = Wk; fo = f0 - 256; outp = g_ampk; ostride = E_; }
    else               { Wp = Wv; fo = f0 - 512; outp = g_V;    ostride = H_; }

    const int tid  = threadIdx.x;
    const int tx   = tid & 15;            // f micro
    const int ty   = tid >> 4;            // m micro
    const int lrow = tid >> 2;            // 0..63 loader row
    const int lk   = (tid & 3) * 8;       // 0,8,16,24 loader k base

    const float* xg = x  + (m0 + lrow) * E_ + lk;
    const float* wg = Wp + (fo + lrow) * E_ + lk;

    float acc[4][4] = {};

    for (int k0 = 0; k0 < E_; k0 += 32) {
        float4 a0 = *(const float4*)(xg + k0);
        float4 a1 = *(const float4*)(xg + k0 + 4);
        float4 b0 = *(const float4*)(wg + k0);
        float4 b1 = *(const float4*)(wg + k0 + 4);
        As[lk+0][lrow] = a0.x; As[lk+1][lrow] = a0.y;
        As[lk+2][lrow] = a0.z; As[lk+3][lrow] = a0.w;
        As[lk+4][lrow] = a1.x; As[lk+5][lrow] = a1.y;
        As[lk+6][lrow] = a1.z; As[lk+7][lrow] = a1.w;
        Bs[lk+0][lrow] = b0.x; Bs[lk+1][lrow] = b0.y;
        Bs[lk+2][lrow] = b0.z; Bs[lk+3][lrow] = b0.w;
        Bs[lk+4][lrow] = b1.x; Bs[lk+5][lrow] = b1.y;
        Bs[lk+6][lrow] = b1.z; Bs[lk+7][lrow] = b1.w;
        __syncthreads();

        #pragma unroll
        for (int kk = 0; kk < 32; kk++) {
            float4 av = *(const float4*)&As[kk][ty * 4];
            float4 bv = *(const float4*)&Bs[kk][tx * 4];
            acc[0][0] = fmaf(av.x, bv.x, acc[0][0]);
            acc[0][1] = fmaf(av.x, bv.y, acc[0][1]);
            acc[0][2] = fmaf(av.x, bv.z, acc[0][2]);
            acc[0][3] = fmaf(av.x, bv.w, acc[0][3]);
            acc[1][0] = fmaf(av.y, bv.x, acc[1][0]);
            acc[1][1] = fmaf(av.y, bv.y, acc[1][1]);
            acc[1][2] = fmaf(av.y, bv.z, acc[1][2]);
            acc[1][3] = fmaf(av.y, bv.w, acc[1][3]);
            acc[2][0] = fmaf(av.z, bv.x, acc[2][0]);
            acc[2][1] = fmaf(av.z, bv.y, acc[2][1]);
            acc[2][2] = fmaf(av.z, bv.z, acc[2][2]);
            acc[2][3] = fmaf(av.z, bv.w, acc[2][3]);
            acc[3][0] = fmaf(av.w, bv.x, acc[3][0]);
            acc[3][1] = fmaf(av.w, bv.y, acc[3][1]);
            acc[3][2] = fmaf(av.w, bv.z, acc[3][2]);
            acc[3][3] = fmaf(av.w, bv.w, acc[3][3]);
        }
        __syncthreads();
    }

    #pragma unroll
    for (int i = 0; i < 4; i++) {
        const int row = m0 + ty * 4 + i;
        float4 v = make_float4(acc[i][0], acc[i][1], acc[i][2], acc[i][3]);
        *(float4*)&outp[row * ostride + fo + tx * 4] = v;
    }
}

// ---------------------------------------------------------------------------
// Kernel 2: per row n, per region (q/k): P = amp^2 / (ssq_amp + EPS*d^2),
// d = ||x_n|| + 1e-12  (psi-normalization folded in algebraically),
// and entropy ent = sum P*lg2(P+EPS).  grid (1024, 2), 256 threads.
// ---------------------------------------------------------------------------
__global__ __launch_bounds__(256) void k2_probs(const float* __restrict__ x)
{
    __shared__ float srA[8], srB[8];
    __shared__ float sInv;

    const int n    = blockIdx.x;
    const int regn = blockIdx.y;
    const float* amp  = (regn ? g_ampk : g_ampq) + n * E_;
    float*       Pout = (regn ? g_Pk   : g_Pq)   + n * E_;
    float*       Eout =  regn ? g_entk : g_entq;

    const int t = threadIdx.x, w = t >> 5, lane = t & 31;
    const float a  = amp[t];
    const float xv = x[n * E_ + t];

    float s1 = a * a, s2 = xv * xv;
    #pragma unroll
    for (int o = 16; o; o >>= 1) {
        s1 += __shfl_xor_sync(0xffffffffu, s1, o);
        s2 += __shfl_xor_sync(0xffffffffu, s2, o);
    }
    if (lane == 0) { srA[w] = s1; srB[w] = s2; }
    __syncthreads();
    if (t == 0) {
        float ssa = 0.f, ssx = 0.f;
        #pragma unroll
        for (int k = 0; k < 8; k++) { ssa += srA[k]; ssx += srB[k]; }
        float d = sqrtf(ssx) + 1e-12f;
        sInv = 1.0f / (ssa + 1e-10f * d * d);
    }
    __syncthreads();

    const float P = a * a * sInv;
    Pout[t] = P;
    float term = P * __log2f(P + 1e-10f);
    #pragma unroll
    for (int o = 16; o; o >>= 1)
        term += __shfl_xor_sync(0xffffffffu, term, o);
    __syncthreads();               // srA free for reuse
    if (lane == 0) srA[w] = term;
    __syncthreads();
    if (t == 0) {
        float e = 0.f;
        #pragma unroll
        for (int k = 0; k < 8; k++) e += srA[k];
        Eout[n] = e;
    }
}

// ---------------------------------------------------------------------------
// Kernel 3: fused JS score + causal row-normalize + attn @ V.
// One CTA handles two adjacent query rows (i0, i1=i0+1) of the same batch:
// Q row loads are reused for both rows (halves L2 traffic below MUFU floor).
// Warp-per-j, P_i rows register-resident, shfl reduction.
// 512 CTAs x 256 threads; smem ~3.3KB -> fully resident grid.
// ---------------------------------------------------------------------------
__global__ __launch_bounds__(256) void k3_attn(float* __restrict__ out)
{
    __shared__ float sScore[2][256];
    __shared__ float sO[2][128];
    __shared__ float sred[2][8];
    __shared__ float sInv[2];

    const int c  = blockIdx.x;        // 0..511
    const int n0 = c * 2;
    const int b  = n0 >> 8;
    const int i0 = n0 & 255;
    const int i1 = i0 + 1;
    const int tid  = threadIdx.x;
    const int w    = tid >> 5;
    const int lane = tid & 31;

    // Register-resident P rows for the two queries (per-warp copy, coalesced).
    float p0[8], p1[8];
    const float* Pq0 = g_Pq + n0 * E_;
    #pragma unroll
    for (int m = 0; m < 8; m++) {
        p0[m] = Pq0[lane + 32 * m];
        p1[m] = Pq0[E_ + lane + 32 * m];
    }
    const float hq0 = g_entq[n0];
    const float hq1 = g_entq[n0 + 1];
    const float* Pkb   = g_Pk   + b * S_ * E_;
    const float* entkb = g_entk + b * S_;

    for (int j = w; j <= i1; j += 8) {
        const float* Qr = Pkb + j * E_;
        float acc0 = 0.f, acc1 = 0.f;
        #pragma unroll
        for (int m = 0; m < 8; m++) {
            float q  = Qr[lane + 32 * m];
            float s0 = p0[m] + q;
            float s1 = p1[m] + q;
            acc0 = fmaf(s0, __log2f(fmaf(0.5f, s0, 1e-10f)), acc0);
            acc1 = fmaf(s1, __log2f(fmaf(0.5f, s1, 1e-10f)), acc1);
        }
        #pragma unroll
        for (int o = 16; o; o >>= 1) {
            acc0 += __shfl_xor_sync(0xffffffffu, acc0, o);
            acc1 += __shfl_xor_sync(0xffffffffu, acc1, o);
        }
        if (lane == 0) {
            const float HL = 0.34657359028f;   // 0.5 * ln(2)
            float hk  = entkb[j];
            float js0 = HL * (hq0 + hk - acc0);
            float js1 = HL * (hq1 + hk - acc1);
            sScore[0][j] = (j <= i0) ? (1.0f - js0) : 0.0f;  // causal mask row i0
            sScore[1][j] = 1.0f - js1;
        }
    }
    __syncthreads();

    // Row L1-normalization sums (scores are positive; fabsf matches reference).
    float v0 = (tid <= i0) ? fabsf(sScore[0][tid]) : 0.f;
    float v1 = (tid <= i1) ? fabsf(sScore[1][tid]) : 0.f;
    #pragma unroll
    for (int o = 16; o; o >>= 1) {
        v0 += __shfl_xor_sync(0xffffffffu, v0, o);
        v1 += __shfl_xor_sync(0xffffffffu, v1, o);
    }
    if (lane == 0) { sred[0][w] = v0; sred[1][w] = v1; }
    __syncthreads();
    if (tid == 0) {
        float s0 = 0.f, s1 = 0.f;
        #pragma unroll
        for (int k = 0; k < 8; k++) { s0 += sred[0][k]; s1 += sred[1][k]; }
        sInv[0] = 1.0f / fmaxf(s0, 1e-12f);
        sInv[1] = 1.0f / fmaxf(s1, 1e-12f);
    }
    __syncthreads();

    // out[i,h] = inv * sum_{j<=i} score[j] * V[j,h]; split j over 2 halves.
    const int half = tid >> 7;
    const int h    = tid & 127;
    const float* Vb = g_V + b * S_ * H_;
    float a0 = 0.f, a1 = 0.f;
    for (int j = half; j <= i1; j += 2) {
        float v = Vb[j * H_ + h];
        a0 = fmaf(sScore[0][j], v, a0);   // sScore[0][i1] == 0 (masked)
        a1 = fmaf(sScore[1][j], v, a1);
    }
    if (half == 1) { sO[0][h] = a0; sO[1][h] = a1; }
    __syncthreads();
    if (half == 0) {
        out[n0 * H_ + h]        = (a0 + sO[0][h]) * sInv[0];
        out[(n0 + 1) * H_ + h]  = (a1 + sO[1][h]) * sInv[1];
    }
}

// ---------------------------------------------------------------------------
// Launch. Inputs per metadata order: x, Wv, Wq, Wk (all float32).
// ---------------------------------------------------------------------------
extern "C" void kernel_launch(void* const* d_in, const int* in_sizes, int n_in,
                              void* d_out, int out_size)
{
    const float* x  = (const float*)d_in[0];
    const float* Wv = (const float*)d_in[1];
    const float* Wq = (const float*)d_in[2];
    const float* Wk = (const float*)d_in[3];
    float* out = (float*)d_out;

    k1_gemm<<<dim3(16, 10), 256>>>(x, Wq, Wk, Wv);
    k2_probs<<<dim3(N_, 2), 256>>>(x);
    k3_attn<<<512, 256>>>(out);
}

// round 5
// speedup vs baseline: 1.0035x; 1.0035x over previous
#include <cuda_runtime.h>
#include <math.h>

// Problem constants (fixed by the dataset)
#define B_ 4
#define S_ 256
#define E_ 256
#define H_ 128
#define N_ (B_ * S_)   // 1024 rows total

// Scratch (static device arrays; allocation-free per harness rules)
__device__ float g_ampq[N_ * E_];
__device__ float g_ampk[N_ * E_];
__device__ float g_V[N_ * H_];
__device__ float g_Pq[N_ * E_];
__device__ float g_Pk[N_ * E_];
__device__ float g_entq[N_];   // sum_e P * lg2(P + 1e-10)
__device__ float g_entk[N_];

// ---------------------------------------------------------------------------
// Kernel 1: C[1024, 640] = x[1024,256] @ [Wq;Wk;Wv]^T   (region per f-tile)
// 64x64 CTA tile, 256 threads, 4x4 micro-tile, k-chunk 32, smem transposed
// so compute reads are float4 (2 LDS.128 + 16 FFMA per kk).
// ---------------------------------------------------------------------------
__global__ __launch_bounds__(256) void k1_gemm(
    const float* __restrict__ x,
    const float* __restrict__ Wq,
    const float* __restrict__ Wk,
    const float* __restrict__ Wv)
{
    __shared__ float As[32][68];  // [k][m], pad 4 keeps float4 alignment
    __shared__ float Bs[32][68];  // [k][f]

    const int m0 = blockIdx.x * 64;       // row tile (0..15)
    const int f0 = blockIdx.y * 64;       // f tile (0..9) over concat 640

    const float* Wp; float* outp; int fo, ostride;
    if (f0 < 256)      { Wp = Wq; fo = f0;       outp = g_ampq; ostride = E_; }
    else if (f0 < 512) { Wp = Wk; fo = f0 - 256; outp = g_ampk; ostride = E_; }
    else               { Wp = Wv; fo = f0 - 512; outp = g_V;    ostride = H_; }

    const int tid  = threadIdx.x;
    const int tx   = tid & 15;            // f micro
    const int ty   = tid >> 4;            // m micro
    const int lrow = tid >> 2;            // 0..63 loader row
    const int lk   = (tid & 3) * 8;       // 0,8,16,24 loader k base

    const float* xg = x  + (m0 + lrow) * E_ + lk;
    const float* wg = Wp + (fo + lrow) * E_ + lk;

    float acc[4][4] = {};

    for (int k0 = 0; k0 < E_; k0 += 32) {
        float4 a0 = *(const float4*)(xg + k0);
        float4 a1 = *(const float4*)(xg + k0 + 4);
        float4 b0 = *(const float4*)(wg + k0);
        float4 b1 = *(const float4*)(wg + k0 + 4);
        As[lk+0][lrow] = a0.x; As[lk+1][lrow] = a0.y;
        As[lk+2][lrow] = a0.z; As[lk+3][lrow] = a0.w;
        As[lk+4][lrow] = a1.x; As[lk+5][lrow] = a1.y;
        As[lk+6][lrow] = a1.z; As[lk+7][lrow] = a1.w;
        Bs[lk+0][lrow] = b0.x; Bs[lk+1][lrow] = b0.y;
        Bs[lk+2][lrow] = b0.z; Bs[lk+3][lrow] = b0.w;
        Bs[lk+4][lrow] = b1.x; Bs[lk+5][lrow] = b1.y;
        Bs[lk+6][lrow] = b1.z; Bs[lk+7][lrow] = b1.w;
        __syncthreads();

        #pragma unroll
        for (int kk = 0; kk < 32; kk++) {
            float4 av = *(const float4*)&As[kk][ty * 4];
            float4 bv = *(const float4*)&Bs[kk][tx * 4];
            acc[0][0] = fmaf(av.x, bv.x, acc[0][0]);
            acc[0][1] = fmaf(av.x, bv.y, acc[0][1]);
            acc[0][2] = fmaf(av.x, bv.z, acc[0][2]);
            acc[0][3] = fmaf(av.x, bv.w, acc[0][3]);
            acc[1][0] = fmaf(av.y, bv.x, acc[1][0]);
            acc[1][1] = fmaf(av.y, bv.y, acc[1][1]);
            acc[1][2] = fmaf(av.y, bv.z, acc[1][2]);
            acc[1][3] = fmaf(av.y, bv.w, acc[1][3]);
            acc[2][0] = fmaf(av.z, bv.x, acc[2][0]);
            acc[2][1] = fmaf(av.z, bv.y, acc[2][1]);
            acc[2][2] = fmaf(av.z, bv.z, acc[2][2]);
            acc[2][3] = fmaf(av.z, bv.w, acc[2][3]);
            acc[3][0] = fmaf(av.w, bv.x, acc[3][0]);
            acc[3][1] = fmaf(av.w, bv.y, acc[3][1]);
            acc[3][2] = fmaf(av.w, bv.z, acc[3][2]);
            acc[3][3] = fmaf(av.w, bv.w, acc[3][3]);
        }
        __syncthreads();
    }

    #pragma unroll
    for (int i = 0; i < 4; i++) {
        const int row = m0 + ty * 4 + i;
        float4 v = make_float4(acc[i][0], acc[i][1], acc[i][2], acc[i][3]);
        *(float4*)&outp[row * ostride + fo + tx * 4] = v;
    }
}

// ---------------------------------------------------------------------------
// Kernel 2: per row n, per region (q/k): P = amp^2 / (ssq_amp + EPS*d^2),
// d = ||x_n|| + 1e-12  (psi-normalization folded in algebraically),
// and entropy ent = sum P*lg2(P+EPS).  grid (1024, 2), 256 threads.
// ---------------------------------------------------------------------------
__global__ __launch_bounds__(256) void k2_probs(const float* __restrict__ x)
{
    __shared__ float srA[8], srB[8];
    __shared__ float sInv;

    const int n    = blockIdx.x;
    const int regn = blockIdx.y;
    const float* amp  = (regn ? g_ampk : g_ampq) + n * E_;
    float*       Pout = (regn ? g_Pk   : g_Pq)   + n * E_;
    float*       Eout =  regn ? g_entk : g_entq;

    const int t = threadIdx.x, w = t >> 5, lane = t & 31;
    const float a  = amp[t];
    const float xv = x[n * E_ + t];

    float s1 = a * a, s2 = xv * xv;
    #pragma unroll
    for (int o = 16; o; o >>= 1) {
        s1 += __shfl_xor_sync(0xffffffffu, s1, o);
        s2 += __shfl_xor_sync(0xffffffffu, s2, o);
    }
    if (lane == 0) { srA[w] = s1; srB[w] = s2; }
    __syncthreads();
    if (t == 0) {
        float ssa = 0.f, ssx = 0.f;
        #pragma unroll
        for (int k = 0; k < 8; k++) { ssa += srA[k]; ssx += srB[k]; }
        float d = sqrtf(ssx) + 1e-12f;
        sInv = 1.0f / (ssa + 1e-10f * d * d);
    }
    __syncthreads();

    const float P = a * a * sInv;
    Pout[t] = P;
    float term = P * __log2f(P + 1e-10f);
    #pragma unroll
    for (int o = 16; o; o >>= 1)
        term += __shfl_xor_sync(0xffffffffu, term, o);
    __syncthreads();               // srA free for reuse
    if (lane == 0) srA[w] = term;
    __syncthreads();
    if (t == 0) {
        float e = 0.f;
        #pragma unroll
        for (int k = 0; k < 8; k++) e += srA[k];
        Eout[n] = e;
    }
}

// ---------------------------------------------------------------------------
// Kernel 3: fused JS score + causal row-normalize + attn @ V.
// One CTA handles two adjacent query rows (i0, i1=i0+1) of the same batch:
// Q row loads are reused for both rows (halves L2 traffic below MUFU floor).
// Warp-per-j, P_i rows register-resident, shfl reduction.
// 512 CTAs x 256 threads; smem ~3.3KB -> fully resident grid.
// ---------------------------------------------------------------------------
__global__ __launch_bounds__(256) void k3_attn(float* __restrict__ out)
{
    __shared__ float sScore[2][256];
    __shared__ float sO[2][128];
    __shared__ float sred[2][8];
    __shared__ float sInv[2];

    const int c  = blockIdx.x;        // 0..511
    const int n0 = c * 2;
    const int b  = n0 >> 8;
    const int i0 = n0 & 255;
    const int i1 = i0 + 1;
    const int tid  = threadIdx.x;
    const int w    = tid >> 5;
    const int lane = tid & 31;

    // Register-resident P rows for the two queries (per-warp copy, coalesced).
    float p0[8], p1[8];
    const float* Pq0 = g_Pq + n0 * E_;
    #pragma unroll
    for (int m = 0; m < 8; m++) {
        p0[m] = Pq0[lane + 32 * m];
        p1[m] = Pq0[E_ + lane + 32 * m];
    }
    const float hq0 = g_entq[n0];
    const float hq1 = g_entq[n0 + 1];
    const float* Pkb   = g_Pk   + b * S_ * E_;
    const float* entkb = g_entk + b * S_;

    for (int j = w; j <= i1; j += 8) {
        const float* Qr = Pkb + j * E_;
        float acc0 = 0.f, acc1 = 0.f;
        #pragma unroll
        for (int m = 0; m < 8; m++) {
            float q  = Qr[lane + 32 * m];
            float s0 = p0[m] + q;
            float s1 = p1[m] + q;
            acc0 = fmaf(s0, __log2f(fmaf(0.5f, s0, 1e-10f)), acc0);
            acc1 = fmaf(s1, __log2f(fmaf(0.5f, s1, 1e-10f)), acc1);
        }
        #pragma unroll
        for (int o = 16; o; o >>= 1) {
            acc0 += __shfl_xor_sync(0xffffffffu, acc0, o);
            acc1 += __shfl_xor_sync(0xffffffffu, acc1, o);
        }
        if (lane == 0) {
            const float HL = 0.34657359028f;   // 0.5 * ln(2)
            float hk  = entkb[j];
            float js0 = HL * (hq0 + hk - acc0);
            float js1 = HL * (hq1 + hk - acc1);
            sScore[0][j] = (j <= i0) ? (1.0f - js0) : 0.0f;  // causal mask row i0
            sScore[1][j] = 1.0f - js1;
        }
    }
    __syncthreads();

    // Row L1-normalization sums (scores are positive; fabsf matches reference).
    float v0 = (tid <= i0) ? fabsf(sScore[0][tid]) : 0.f;
    float v1 = (tid <= i1) ? fabsf(sScore[1][tid]) : 0.f;
    #pragma unroll
    for (int o = 16; o; o >>= 1) {
        v0 += __shfl_xor_sync(0xffffffffu, v0, o);
        v1 += __shfl_xor_sync(0xffffffffu, v1, o);
    }
    if (lane == 0) { sred[0][w] = v0; sred[1][w] = v1; }
    __syncthreads();
    if (tid == 0) {
        float s0 = 0.f, s1 = 0.f;
        #pragma unroll
        for (int k = 0; k < 8; k++) { s0 += sred[0][k]; s1 += sred[1][k]; }
        sInv[0] = 1.0f / fmaxf(s0, 1e-12f);
        sInv[1] = 1.0f / fmaxf(s1, 1e-12f);
    }
    __syncthreads();

    // out[i,h] = inv * sum_{j<=i} score[j] * V[j,h]; split j over 2 halves.
    const int half = tid >> 7;
    const int h    = tid & 127;
    const float* Vb = g_V + b * S_ * H_;
    float a0 = 0.f, a1 = 0.f;
    for (int j = half; j <= i1; j += 2) {
        float v = Vb[j * H_ + h];
        a0 = fmaf(sScore[0][j], v, a0);   // sScore[0][i1] == 0 (masked)
        a1 = fmaf(sScore[1][j], v, a1);
    }
    if (half == 1) { sO[0][h] = a0; sO[1][h] = a1; }
    __syncthreads();
    if (half == 0) {
        out[n0 * H_ + h]        = (a0 + sO[0][h]) * sInv[0];
        out[(n0 + 1) * H_ + h]  = (a1 + sO[1][h]) * sInv[1];
    }
}

// ---------------------------------------------------------------------------
// Launch. Inputs per metadata order: x, Wv, Wq, Wk (all float32).
// ---------------------------------------------------------------------------
extern "C" void kernel_launch(void* const* d_in, const int* in_sizes, int n_in,
                              void* d_out, int out_size)
{
    const float* x  = (const float*)d_in[0];
    const float* Wv = (const float*)d_in[1];
    const float* Wq = (const float*)d_in[2];
    const float* Wk = (const float*)d_in[3];
    float* out = (float*)d_out;

    k1_gemm<<<dim3(16, 10), 256>>>(x, Wq, Wk, Wv);
    k2_probs<<<dim3(N_, 2), 256>>>(x);
    k3_attn<<<512, 256>>>(out);
}